// round 3
// baseline (speedup 1.0000x reference)
#include <cuda_runtime.h>
#include <cuda_fp16.h>
#include <cstdint>

#define N_NODES 100000
#define N_EDGES 3200000
#define IN_DIM  256
#define HIDDEN  128
#define OUT_DIM 64

typedef unsigned long long ull;

// ---------------- device scratch (static; no cudaMalloc) ----------------
__device__ __align__(128) __half g_h0[(size_t)N_NODES * HIDDEN];  // X @ W1 (fp16)
__device__ __align__(128) float  g_h2[(size_t)N_NODES * OUT_DIM]; // relu(A@h0) @ W2 (fp32)
__device__ int  g_cnt[N_NODES];
__device__ int  g_row_ptr[N_NODES + 1];
__device__ int  g_cursor[N_NODES];
__device__ __align__(128) int2 g_edges[N_EDGES];                  // {src, val bits}
#define SCAN_BLOCKS 98
__device__ int  g_bsum[SCAN_BLOCKS];
__device__ int  g_boff[SCAN_BLOCKS];

// ---------------- f32x2 helpers ----------------
__device__ __forceinline__ ull pack2(float x, float y) {
    ull r; asm("mov.b64 %0,{%1,%2};" : "=l"(r) : "f"(x), "f"(y)); return r;
}
__device__ __forceinline__ void ffma2(ull& d, ull a, ull b) {
    asm("fma.rn.f32x2 %0,%1,%2,%0;" : "+l"(d) : "l"(a), "l"(b));
}
__device__ __forceinline__ void unpack2(ull v, float& lo, float& hi) {
    asm("mov.b64 {%0,%1},%2;" : "=f"(lo), "=f"(hi) : "l"(v));
}
__device__ __forceinline__ uint32_t f32x2_to_h2(ull v) {
    float lo, hi; unpack2(v, lo, hi);
    __half2 h = __floats2half2_rn(lo, hi);
    return *reinterpret_cast<uint32_t*>(&h);
}

// ---------------- CSR build ----------------
__global__ void zero_cnt_kernel() {
    int i = blockIdx.x * blockDim.x + threadIdx.x;
    if (i < N_NODES) g_cnt[i] = 0;
}

__global__ void hist_kernel(const int* __restrict__ edge_dst) {
    int e = blockIdx.x * blockDim.x + threadIdx.x;
    if (e < N_EDGES) atomicAdd(&g_cnt[edge_dst[e]], 1);
}

__device__ __forceinline__ int warp_incl_scan(int v) {
    int lane = threadIdx.x & 31;
    #pragma unroll
    for (int o = 1; o < 32; o <<= 1) {
        int n = __shfl_up_sync(0xffffffffu, v, o);
        if (lane >= o) v += n;
    }
    return v;
}

__global__ void scan_reduce_kernel() {
    int i = blockIdx.x * 1024 + threadIdx.x;
    int v = (i < N_NODES) ? g_cnt[i] : 0;
    #pragma unroll
    for (int o = 16; o > 0; o >>= 1) v += __shfl_down_sync(0xffffffffu, v, o);
    __shared__ int ws[32];
    int wid = threadIdx.x >> 5, lane = threadIdx.x & 31;
    if (lane == 0) ws[wid] = v;
    __syncthreads();
    if (wid == 0) {
        v = ws[lane];
        #pragma unroll
        for (int o = 16; o > 0; o >>= 1) v += __shfl_down_sync(0xffffffffu, v, o);
        if (lane == 0) g_bsum[blockIdx.x] = v;
    }
}

__global__ void scan_partials_kernel() {
    int t = threadIdx.x;
    int v = (t < SCAN_BLOCKS) ? g_bsum[t] : 0;
    int incl = warp_incl_scan(v);
    __shared__ int ws[4];
    int wid = t >> 5, lane = t & 31;
    if (lane == 31) ws[wid] = incl;
    __syncthreads();
    int off = 0;
    #pragma unroll
    for (int w = 0; w < 4; ++w) if (w < wid) off += ws[w];
    incl += off;
    if (t < SCAN_BLOCKS) g_boff[t] = incl - v;  // exclusive
    if (t == 0) g_row_ptr[N_NODES] = N_EDGES;
}

__global__ void scan_final_kernel() {
    int i = blockIdx.x * 1024 + threadIdx.x;
    int v = (i < N_NODES) ? g_cnt[i] : 0;
    int incl = warp_incl_scan(v);
    __shared__ int ws[32];
    int wid = threadIdx.x >> 5, lane = threadIdx.x & 31;
    if (lane == 31) ws[wid] = incl;
    __syncthreads();
    if (wid == 0) { int w = warp_incl_scan(ws[lane]); ws[lane] = w; }
    __syncthreads();
    int off = g_boff[blockIdx.x] + ((wid > 0) ? ws[wid - 1] : 0);
    if (i < N_NODES) {
        int ex = off + incl - v;
        g_row_ptr[i] = ex;
        g_cursor[i]  = ex;
    }
}

__global__ void scatter_kernel(const int* __restrict__ edge_src,
                               const int* __restrict__ edge_dst,
                               const float* __restrict__ adj_vals) {
    int e = blockIdx.x * blockDim.x + threadIdx.x;
    if (e >= N_EDGES) return;
    int d = edge_dst[e];
    int pos = atomicAdd(&g_cursor[d], 1);
    g_edges[pos] = make_int2(edge_src[e], __float_as_int(adj_vals[e]));
}

// ---------------- FFMA2 GEMM -> fp16 output: C[M,TN] = half(A[M,K] @ B[K,TN]) ----------------
template<int TK, int TN>
__global__ __launch_bounds__(256, 2)
void gemm_f32x2_h16out_kernel(const float* __restrict__ A, const float* __restrict__ B,
                              __half* __restrict__ C, int M, int K) {
    constexpr int NCOL = TN / 16;   // 8 cols per thread
    constexpr int NCP  = NCOL / 2;  // 4 col pairs
    __shared__ float As[128][TK + 4];
    __shared__ float Bs[TK][TN];

    const int t  = threadIdx.x;
    const int tr = t >> 4;
    const int tc = t & 15;
    const int row0 = blockIdx.x * 128;

    ull acc[8][NCP];
    #pragma unroll
    for (int r = 0; r < 8; ++r)
        #pragma unroll
        for (int c = 0; c < NCP; ++c) acc[r][c] = 0ull;

    for (int k0 = 0; k0 < K; k0 += TK) {
        constexpr int AF4 = 128 * TK / 4;
        #pragma unroll
        for (int i = 0; i < AF4 / 256; ++i) {
            int idx = t + i * 256;
            int kq = idx % (TK / 4);
            int m  = idx / (TK / 4);
            int gr = row0 + m;
            float4 v = make_float4(0.f, 0.f, 0.f, 0.f);
            if (gr < M) v = *reinterpret_cast<const float4*>(A + (size_t)gr * K + k0 + kq * 4);
            *reinterpret_cast<float4*>(&As[m][kq * 4]) = v;
        }
        constexpr int BF4 = TK * TN / 4;
        #pragma unroll
        for (int i = 0; i < BF4 / 256; ++i) {
            int idx = t + i * 256;
            int nq = idx % (TN / 4);
            int kr = idx / (TN / 4);
            *reinterpret_cast<float4*>(&Bs[kr][nq * 4]) =
                *reinterpret_cast<const float4*>(B + (size_t)(k0 + kr) * TN + nq * 4);
        }
        __syncthreads();

        #pragma unroll 4
        for (int kk = 0; kk < TK; ++kk) {
            ull b[NCP];
            #pragma unroll
            for (int c = 0; c < NCP; ++c)
                b[c] = *reinterpret_cast<const ull*>(&Bs[kk][tc * NCOL + 2 * c]);
            #pragma unroll
            for (int r = 0; r < 8; ++r) {
                float a = As[tr * 8 + r][kk];
                ull pa = pack2(a, a);
                #pragma unroll
                for (int c = 0; c < NCP; ++c) ffma2(acc[r][c], pa, b[c]);
            }
        }
        __syncthreads();
    }

    #pragma unroll
    for (int r = 0; r < 8; ++r) {
        int gr = row0 + tr * 8 + r;
        if (gr >= M) continue;
        uint4 v;
        v.x = f32x2_to_h2(acc[r][0]);
        v.y = f32x2_to_h2(acc[r][1]);
        v.z = f32x2_to_h2(acc[r][2]);
        v.w = f32x2_to_h2(acc[r][3]);
        *reinterpret_cast<uint4*>(C + (size_t)gr * TN + tc * NCOL) = v;
    }
}

// ---------------- fused: h2 = relu(A @ h0_fp16) @ W2 ----------------
// warp-per-row (8 rows per warp); gather fp16, accumulate fp32; then
// per-row 128x64 GEMV against smem-resident W2 via FFMA2.
#define ROWS_PER_WARP 8
__global__ __launch_bounds__(256)
void spmm1_fused_kernel(const __half* __restrict__ h0, const float* __restrict__ w2,
                        float* __restrict__ h2) {
    __shared__ float W2s[HIDDEN * OUT_DIM];   // 32 KB, [k][n] row-major
    __shared__ float h1s[8][HIDDEN];          // per-warp relu'd row

    for (int i = threadIdx.x; i < HIDDEN * OUT_DIM; i += 256)
        W2s[i] = w2[i];
    __syncthreads();

    const int wid  = threadIdx.x >> 5;
    const int lane = threadIdx.x & 31;
    const int c    = lane * 4;
    const int row0 = (blockIdx.x * 8 + wid) * ROWS_PER_WARP;

    for (int r = 0; r < ROWS_PER_WARP; ++r) {
        int row = row0 + r;
        if (row >= N_NODES) break;
        int beg = g_row_ptr[row];
        int end = g_row_ptr[row + 1];

        float4 acc = make_float4(0.f, 0.f, 0.f, 0.f);
        int e = beg;
        int e4 = beg + ((end - beg) & ~3);
        for (; e < e4; e += 4) {
            int2 d0 = __ldg(&g_edges[e + 0]);
            int2 d1 = __ldg(&g_edges[e + 1]);
            int2 d2 = __ldg(&g_edges[e + 2]);
            int2 d3 = __ldg(&g_edges[e + 3]);
            uint2 r0 = __ldg((const uint2*)(h0 + ((size_t)d0.x << 7) + c));
            uint2 r1 = __ldg((const uint2*)(h0 + ((size_t)d1.x << 7) + c));
            uint2 r2 = __ldg((const uint2*)(h0 + ((size_t)d2.x << 7) + c));
            uint2 r3 = __ldg((const uint2*)(h0 + ((size_t)d3.x << 7) + c));
            float v0 = __int_as_float(d0.y), v1 = __int_as_float(d1.y);
            float v2 = __int_as_float(d2.y), v3 = __int_as_float(d3.y);
            float2 a0 = __half22float2(*reinterpret_cast<__half2*>(&r0.x));
            float2 b0 = __half22float2(*reinterpret_cast<__half2*>(&r0.y));
            float2 a1 = __half22float2(*reinterpret_cast<__half2*>(&r1.x));
            float2 b1 = __half22float2(*reinterpret_cast<__half2*>(&r1.y));
            float2 a2 = __half22float2(*reinterpret_cast<__half2*>(&r2.x));
            float2 b2 = __half22float2(*reinterpret_cast<__half2*>(&r2.y));
            float2 a3 = __half22float2(*reinterpret_cast<__half2*>(&r3.x));
            float2 b3 = __half22float2(*reinterpret_cast<__half2*>(&r3.y));
            acc.x = fmaf(v0, a0.x, acc.x); acc.y = fmaf(v0, a0.y, acc.y);
            acc.z = fmaf(v0, b0.x, acc.z); acc.w = fmaf(v0, b0.y, acc.w);
            acc.x = fmaf(v1, a1.x, acc.x); acc.y = fmaf(v1, a1.y, acc.y);
            acc.z = fmaf(v1, b1.x, acc.z); acc.w = fmaf(v1, b1.y, acc.w);
            acc.x = fmaf(v2, a2.x, acc.x); acc.y = fmaf(v2, a2.y, acc.y);
            acc.z = fmaf(v2, b2.x, acc.z); acc.w = fmaf(v2, b2.y, acc.w);
            acc.x = fmaf(v3, a3.x, acc.x); acc.y = fmaf(v3, a3.y, acc.y);
            acc.z = fmaf(v3, b3.x, acc.z); acc.w = fmaf(v3, b3.y, acc.w);
        }
        for (; e < end; ++e) {
            int2 d0 = __ldg(&g_edges[e]);
            float v0 = __int_as_float(d0.y);
            uint2 r0 = __ldg((const uint2*)(h0 + ((size_t)d0.x << 7) + c));
            float2 a0 = __half22float2(*reinterpret_cast<__half2*>(&r0.x));
            float2 b0 = __half22float2(*reinterpret_cast<__half2*>(&r0.y));
            acc.x = fmaf(v0, a0.x, acc.x); acc.y = fmaf(v0, a0.y, acc.y);
            acc.z = fmaf(v0, b0.x, acc.z); acc.w = fmaf(v0, b0.y, acc.w);
        }

        float4 h1v = make_float4(fmaxf(acc.x, 0.f), fmaxf(acc.y, 0.f),
                                 fmaxf(acc.z, 0.f), fmaxf(acc.w, 0.f));
        *reinterpret_cast<float4*>(&h1s[wid][c]) = h1v;
        __syncwarp();

        // h2[row][n0..n0+1] = sum_k h1[k] * W2[k][n0..n0+1]
        ull acc2 = 0ull;
        #pragma unroll 8
        for (int k = 0; k < HIDDEN; ++k) {
            float a = h1s[wid][k];
            ull b = *reinterpret_cast<const ull*>(&W2s[k * OUT_DIM + lane * 2]);
            ffma2(acc2, pack2(a, a), b);
        }
        float o0, o1; unpack2(acc2, o0, o1);
        *reinterpret_cast<float2*>(h2 + (size_t)row * OUT_DIM + lane * 2) =
            make_float2(o0, o1);
        __syncwarp();
    }
}

// ---------------- layer-2 SpMM: out = A @ h2 (fp32), half-warp per row ----------------
__global__ void spmm64_kernel(const float* __restrict__ h, float* __restrict__ out) {
    int gt = blockIdx.x * blockDim.x + threadIdx.x;
    int row = gt >> 4;
    if (row >= N_NODES) return;
    int lane16 = threadIdx.x & 15;
    int beg = g_row_ptr[row];
    int end = g_row_ptr[row + 1];
    int c = lane16 * 4;
    float4 acc = make_float4(0.f, 0.f, 0.f, 0.f);

    int e = beg;
    int e4 = beg + ((end - beg) & ~3);
    for (; e < e4; e += 4) {
        int2 d0 = __ldg(&g_edges[e + 0]);
        int2 d1 = __ldg(&g_edges[e + 1]);
        int2 d2 = __ldg(&g_edges[e + 2]);
        int2 d3 = __ldg(&g_edges[e + 3]);
        float4 a0 = *reinterpret_cast<const float4*>(h + ((size_t)d0.x << 6) + c);
        float4 a1 = *reinterpret_cast<const float4*>(h + ((size_t)d1.x << 6) + c);
        float4 a2 = *reinterpret_cast<const float4*>(h + ((size_t)d2.x << 6) + c);
        float4 a3 = *reinterpret_cast<const float4*>(h + ((size_t)d3.x << 6) + c);
        float v0 = __int_as_float(d0.y), v1 = __int_as_float(d1.y);
        float v2 = __int_as_float(d2.y), v3 = __int_as_float(d3.y);
        acc.x = fmaf(v0, a0.x, acc.x); acc.y = fmaf(v0, a0.y, acc.y);
        acc.z = fmaf(v0, a0.z, acc.z); acc.w = fmaf(v0, a0.w, acc.w);
        acc.x = fmaf(v1, a1.x, acc.x); acc.y = fmaf(v1, a1.y, acc.y);
        acc.z = fmaf(v1, a1.z, acc.z); acc.w = fmaf(v1, a1.w, acc.w);
        acc.x = fmaf(v2, a2.x, acc.x); acc.y = fmaf(v2, a2.y, acc.y);
        acc.z = fmaf(v2, a2.z, acc.z); acc.w = fmaf(v2, a2.w, acc.w);
        acc.x = fmaf(v3, a3.x, acc.x); acc.y = fmaf(v3, a3.y, acc.y);
        acc.z = fmaf(v3, a3.z, acc.z); acc.w = fmaf(v3, a3.w, acc.w);
    }
    for (; e < end; ++e) {
        int2 d0 = __ldg(&g_edges[e]);
        float v0 = __int_as_float(d0.y);
        float4 a0 = *reinterpret_cast<const float4*>(h + ((size_t)d0.x << 6) + c);
        acc.x = fmaf(v0, a0.x, acc.x); acc.y = fmaf(v0, a0.y, acc.y);
        acc.z = fmaf(v0, a0.z, acc.z); acc.w = fmaf(v0, a0.w, acc.w);
    }
    *reinterpret_cast<float4*>(out + ((size_t)row << 6) + c) = acc;
}

// ---------------- launch ----------------
extern "C" void kernel_launch(void* const* d_in, const int* in_sizes, int n_in,
                              void* d_out, int out_size) {
    const float* x        = (const float*)d_in[0];
    const float* adj_vals = (const float*)d_in[1];
    const float* w1       = (const float*)d_in[2];
    const float* w2       = (const float*)d_in[3];
    const int*   edge_src = (const int*)d_in[4];
    const int*   edge_dst = (const int*)d_in[5];
    float* out = (float*)d_out;

    __half* p_h0; float* p_h2;
    cudaGetSymbolAddress((void**)&p_h0, g_h0);
    cudaGetSymbolAddress((void**)&p_h2, g_h2);

    const int TPB = 256;

    // CSR build
    zero_cnt_kernel<<<(N_NODES + TPB - 1) / TPB, TPB>>>();
    hist_kernel<<<(N_EDGES + TPB - 1) / TPB, TPB>>>(edge_dst);
    scan_reduce_kernel<<<SCAN_BLOCKS, 1024>>>();
    scan_partials_kernel<<<1, 128>>>();
    scan_final_kernel<<<SCAN_BLOCKS, 1024>>>();
    scatter_kernel<<<(N_EDGES + TPB - 1) / TPB, TPB>>>(edge_src, edge_dst, adj_vals);

    // layer 1: h0 = half(X @ W1)
    gemm_f32x2_h16out_kernel<32, HIDDEN><<<(N_NODES + 127) / 128, 256>>>(x, w1, p_h0, N_NODES, IN_DIM);

    // fused: h2 = relu(A @ h0) @ W2
    {
        int warps = (N_NODES + ROWS_PER_WARP - 1) / ROWS_PER_WARP;
        int blocks = (warps + 7) / 8;
        spmm1_fused_kernel<<<blocks, 256>>>(p_h0, w2, p_h2);
    }

    // out = A @ h2
    spmm64_kernel<<<(N_NODES * 16 + TPB - 1) / TPB, TPB>>>(p_h2, out);
}

// round 4
// speedup vs baseline: 1.1850x; 1.1850x over previous
#include <cuda_runtime.h>
#include <cuda_fp16.h>
#include <cstdint>

#define N_NODES 100000
#define N_EDGES 3200000
#define IN_DIM  256
#define HIDDEN  128
#define OUT_DIM 64

typedef unsigned long long ull;

// ---------------- device scratch (static; no cudaMalloc) ----------------
__device__ __align__(128) __half g_h0[(size_t)N_NODES * HIDDEN];  // X @ W1 (fp16)
__device__ __align__(128) __half g_h1[(size_t)N_NODES * HIDDEN];  // relu(A @ h0) (fp16)
__device__ __align__(128) __half g_h2[(size_t)N_NODES * OUT_DIM]; // h1 @ W2 (fp16)
__device__ int  g_cnt[N_NODES];
__device__ int  g_row_ptr[N_NODES + 1];
__device__ int  g_cursor[N_NODES];
__device__ __align__(128) int2 g_edges[N_EDGES];                  // {src, val bits}
#define SCAN_BLOCKS 98
__device__ int  g_bsum[SCAN_BLOCKS];
__device__ int  g_boff[SCAN_BLOCKS];

// ---------------- f32x2 helpers ----------------
__device__ __forceinline__ ull pack2(float x, float y) {
    ull r; asm("mov.b64 %0,{%1,%2};" : "=l"(r) : "f"(x), "f"(y)); return r;
}
__device__ __forceinline__ void ffma2(ull& d, ull a, ull b) {
    asm("fma.rn.f32x2 %0,%1,%2,%0;" : "+l"(d) : "l"(a), "l"(b));
}
__device__ __forceinline__ void unpack2(ull v, float& lo, float& hi) {
    asm("mov.b64 {%0,%1},%2;" : "=f"(lo), "=f"(hi) : "l"(v));
}
__device__ __forceinline__ uint32_t f32x2_to_h2(ull v) {
    float lo, hi; unpack2(v, lo, hi);
    __half2 h = __floats2half2_rn(lo, hi);
    return *reinterpret_cast<uint32_t*>(&h);
}

// ---------------- CSR build ----------------
__global__ void zero_cnt_kernel() {
    int i = blockIdx.x * blockDim.x + threadIdx.x;
    if (i < N_NODES) g_cnt[i] = 0;
}

__global__ void hist_kernel(const int* __restrict__ edge_dst) {
    int e = blockIdx.x * blockDim.x + threadIdx.x;
    if (e < N_EDGES) atomicAdd(&g_cnt[edge_dst[e]], 1);
}

__device__ __forceinline__ int warp_incl_scan(int v) {
    int lane = threadIdx.x & 31;
    #pragma unroll
    for (int o = 1; o < 32; o <<= 1) {
        int n = __shfl_up_sync(0xffffffffu, v, o);
        if (lane >= o) v += n;
    }
    return v;
}

__global__ void scan_reduce_kernel() {
    int i = blockIdx.x * 1024 + threadIdx.x;
    int v = (i < N_NODES) ? g_cnt[i] : 0;
    #pragma unroll
    for (int o = 16; o > 0; o >>= 1) v += __shfl_down_sync(0xffffffffu, v, o);
    __shared__ int ws[32];
    int wid = threadIdx.x >> 5, lane = threadIdx.x & 31;
    if (lane == 0) ws[wid] = v;
    __syncthreads();
    if (wid == 0) {
        v = ws[lane];
        #pragma unroll
        for (int o = 16; o > 0; o >>= 1) v += __shfl_down_sync(0xffffffffu, v, o);
        if (lane == 0) g_bsum[blockIdx.x] = v;
    }
}

__global__ void scan_partials_kernel() {
    int t = threadIdx.x;
    int v = (t < SCAN_BLOCKS) ? g_bsum[t] : 0;
    int incl = warp_incl_scan(v);
    __shared__ int ws[4];
    int wid = t >> 5, lane = t & 31;
    if (lane == 31) ws[wid] = incl;
    __syncthreads();
    int off = 0;
    #pragma unroll
    for (int w = 0; w < 4; ++w) if (w < wid) off += ws[w];
    incl += off;
    if (t < SCAN_BLOCKS) g_boff[t] = incl - v;  // exclusive
    if (t == 0) g_row_ptr[N_NODES] = N_EDGES;
}

__global__ void scan_final_kernel() {
    int i = blockIdx.x * 1024 + threadIdx.x;
    int v = (i < N_NODES) ? g_cnt[i] : 0;
    int incl = warp_incl_scan(v);
    __shared__ int ws[32];
    int wid = threadIdx.x >> 5, lane = threadIdx.x & 31;
    if (lane == 31) ws[wid] = incl;
    __syncthreads();
    if (wid == 0) { int w = warp_incl_scan(ws[lane]); ws[lane] = w; }
    __syncthreads();
    int off = g_boff[blockIdx.x] + ((wid > 0) ? ws[wid - 1] : 0);
    if (i < N_NODES) {
        int ex = off + incl - v;
        g_row_ptr[i] = ex;
        g_cursor[i]  = ex;
    }
}

__global__ void scatter_kernel(const int* __restrict__ edge_src,
                               const int* __restrict__ edge_dst,
                               const float* __restrict__ adj_vals) {
    int e = blockIdx.x * blockDim.x + threadIdx.x;
    if (e >= N_EDGES) return;
    int d = edge_dst[e];
    int pos = atomicAdd(&g_cursor[d], 1);
    g_edges[pos] = make_int2(edge_src[e], __float_as_int(adj_vals[e]));
}

// ---------------- FFMA2 GEMM (fp32 A) -> fp16 out ----------------
template<int TK, int TN>
__global__ __launch_bounds__(256, 2)
void gemm_f32_h16out_kernel(const float* __restrict__ A, const float* __restrict__ B,
                            __half* __restrict__ C, int M, int K) {
    constexpr int NCOL = TN / 16;
    constexpr int NCP  = NCOL / 2;
    __shared__ float As[128][TK + 4];
    __shared__ float Bs[TK][TN];

    const int t  = threadIdx.x;
    const int tr = t >> 4;
    const int tc = t & 15;
    const int row0 = blockIdx.x * 128;

    ull acc[8][NCP];
    #pragma unroll
    for (int r = 0; r < 8; ++r)
        #pragma unroll
        for (int c = 0; c < NCP; ++c) acc[r][c] = 0ull;

    for (int k0 = 0; k0 < K; k0 += TK) {
        constexpr int AF4 = 128 * TK / 4;
        #pragma unroll
        for (int i = 0; i < AF4 / 256; ++i) {
            int idx = t + i * 256;
            int kq = idx % (TK / 4);
            int m  = idx / (TK / 4);
            int gr = row0 + m;
            float4 v = make_float4(0.f, 0.f, 0.f, 0.f);
            if (gr < M) v = *reinterpret_cast<const float4*>(A + (size_t)gr * K + k0 + kq * 4);
            *reinterpret_cast<float4*>(&As[m][kq * 4]) = v;
        }
        constexpr int BF4 = TK * TN / 4;
        #pragma unroll
        for (int i = 0; i < BF4 / 256; ++i) {
            int idx = t + i * 256;
            int nq = idx % (TN / 4);
            int kr = idx / (TN / 4);
            *reinterpret_cast<float4*>(&Bs[kr][nq * 4]) =
                *reinterpret_cast<const float4*>(B + (size_t)(k0 + kr) * TN + nq * 4);
        }
        __syncthreads();

        #pragma unroll 4
        for (int kk = 0; kk < TK; ++kk) {
            ull b[NCP];
            #pragma unroll
            for (int c = 0; c < NCP; ++c)
                b[c] = *reinterpret_cast<const ull*>(&Bs[kk][tc * NCOL + 2 * c]);
            #pragma unroll
            for (int r = 0; r < 8; ++r) {
                float a = As[tr * 8 + r][kk];
                ull pa = pack2(a, a);
                #pragma unroll
                for (int c = 0; c < NCP; ++c) ffma2(acc[r][c], pa, b[c]);
            }
        }
        __syncthreads();
    }

    #pragma unroll
    for (int r = 0; r < 8; ++r) {
        int gr = row0 + tr * 8 + r;
        if (gr >= M) continue;
        #pragma unroll
        for (int q = 0; q < NCP / 2; ++q) {
            uint2 v;
            v.x = f32x2_to_h2(acc[r][2 * q + 0]);
            v.y = f32x2_to_h2(acc[r][2 * q + 1]);
            *reinterpret_cast<uint2*>(C + (size_t)gr * TN + tc * NCOL + q * 4) = v;
        }
    }
}

// ---------------- FFMA2 GEMM (fp16 A) -> fp16 out ----------------
template<int TK, int TN>
__global__ __launch_bounds__(256, 2)
void gemm_h16_h16out_kernel(const __half* __restrict__ A, const float* __restrict__ B,
                            __half* __restrict__ C, int M, int K) {
    constexpr int NCOL = TN / 16;
    constexpr int NCP  = NCOL / 2;
    __shared__ float As[128][TK + 4];
    __shared__ float Bs[TK][TN];

    const int t  = threadIdx.x;
    const int tr = t >> 4;
    const int tc = t & 15;
    const int row0 = blockIdx.x * 128;

    ull acc[8][NCP];
    #pragma unroll
    for (int r = 0; r < 8; ++r)
        #pragma unroll
        for (int c = 0; c < NCP; ++c) acc[r][c] = 0ull;

    for (int k0 = 0; k0 < K; k0 += TK) {
        // A tile: fp16 global -> fp32 smem (8 halves per uint4 load)
        constexpr int AG = 128 * TK / 8;
        #pragma unroll
        for (int i = 0; i < AG / 256; ++i) {
            int idx = t + i * 256;
            int k8 = idx % (TK / 8);
            int m  = idx / (TK / 8);
            int gr = row0 + m;
            float f[8] = {};
            if (gr < M) {
                uint4 v = *reinterpret_cast<const uint4*>(A + (size_t)gr * K + k0 + k8 * 8);
                float2 p0 = __half22float2(*reinterpret_cast<__half2*>(&v.x));
                float2 p1 = __half22float2(*reinterpret_cast<__half2*>(&v.y));
                float2 p2 = __half22float2(*reinterpret_cast<__half2*>(&v.z));
                float2 p3 = __half22float2(*reinterpret_cast<__half2*>(&v.w));
                f[0] = p0.x; f[1] = p0.y; f[2] = p1.x; f[3] = p1.y;
                f[4] = p2.x; f[5] = p2.y; f[6] = p3.x; f[7] = p3.y;
            }
            #pragma unroll
            for (int q = 0; q < 2; ++q)
                *reinterpret_cast<float4*>(&As[m][k8 * 8 + q * 4]) =
                    make_float4(f[q * 4], f[q * 4 + 1], f[q * 4 + 2], f[q * 4 + 3]);
        }
        constexpr int BF4 = TK * TN / 4;
        #pragma unroll
        for (int i = 0; i < BF4 / 256; ++i) {
            int idx = t + i * 256;
            int nq = idx % (TN / 4);
            int kr = idx / (TN / 4);
            *reinterpret_cast<float4*>(&Bs[kr][nq * 4]) =
                *reinterpret_cast<const float4*>(B + (size_t)(k0 + kr) * TN + nq * 4);
        }
        __syncthreads();

        #pragma unroll 4
        for (int kk = 0; kk < TK; ++kk) {
            ull b[NCP];
            #pragma unroll
            for (int c = 0; c < NCP; ++c)
                b[c] = *reinterpret_cast<const ull*>(&Bs[kk][tc * NCOL + 2 * c]);
            #pragma unroll
            for (int r = 0; r < 8; ++r) {
                float a = As[tr * 8 + r][kk];
                ull pa = pack2(a, a);
                #pragma unroll
                for (int c = 0; c < NCP; ++c) ffma2(acc[r][c], pa, b[c]);
            }
        }
        __syncthreads();
    }

    #pragma unroll
    for (int r = 0; r < 8; ++r) {
        int gr = row0 + tr * 8 + r;
        if (gr >= M) continue;
        #pragma unroll
        for (int q = 0; q < NCP / 2; ++q) {
            uint2 v;
            v.x = f32x2_to_h2(acc[r][2 * q + 0]);
            v.y = f32x2_to_h2(acc[r][2 * q + 1]);
            *reinterpret_cast<uint2*>(C + (size_t)gr * TN + tc * NCOL + q * 4) = v;
        }
    }
}

// ---------------- spmm1: h1 = relu(A @ h0_fp16), fp16 out; warp-per-row ----------------
__global__ void spmm1_relu_kernel(const __half* __restrict__ h0, __half* __restrict__ h1) {
    int row = (int)((blockIdx.x * blockDim.x + threadIdx.x) >> 5);
    if (row >= N_NODES) return;
    int lane = threadIdx.x & 31;
    int beg = g_row_ptr[row];
    int end = g_row_ptr[row + 1];
    int c = lane * 4;
    float4 acc = make_float4(0.f, 0.f, 0.f, 0.f);

    int e = beg;
    int e4 = beg + ((end - beg) & ~3);
    for (; e < e4; e += 4) {
        int2 d0 = __ldg(&g_edges[e + 0]);
        int2 d1 = __ldg(&g_edges[e + 1]);
        int2 d2 = __ldg(&g_edges[e + 2]);
        int2 d3 = __ldg(&g_edges[e + 3]);
        uint2 r0 = __ldg((const uint2*)(h0 + ((size_t)d0.x << 7) + c));
        uint2 r1 = __ldg((const uint2*)(h0 + ((size_t)d1.x << 7) + c));
        uint2 r2 = __ldg((const uint2*)(h0 + ((size_t)d2.x << 7) + c));
        uint2 r3 = __ldg((const uint2*)(h0 + ((size_t)d3.x << 7) + c));
        float v0 = __int_as_float(d0.y), v1 = __int_as_float(d1.y);
        float v2 = __int_as_float(d2.y), v3 = __int_as_float(d3.y);
        float2 a0 = __half22float2(*reinterpret_cast<__half2*>(&r0.x));
        float2 b0 = __half22float2(*reinterpret_cast<__half2*>(&r0.y));
        float2 a1 = __half22float2(*reinterpret_cast<__half2*>(&r1.x));
        float2 b1 = __half22float2(*reinterpret_cast<__half2*>(&r1.y));
        float2 a2 = __half22float2(*reinterpret_cast<__half2*>(&r2.x));
        float2 b2 = __half22float2(*reinterpret_cast<__half2*>(&r2.y));
        float2 a3 = __half22float2(*reinterpret_cast<__half2*>(&r3.x));
        float2 b3 = __half22float2(*reinterpret_cast<__half2*>(&r3.y));
        acc.x = fmaf(v0, a0.x, acc.x); acc.y = fmaf(v0, a0.y, acc.y);
        acc.z = fmaf(v0, b0.x, acc.z); acc.w = fmaf(v0, b0.y, acc.w);
        acc.x = fmaf(v1, a1.x, acc.x); acc.y = fmaf(v1, a1.y, acc.y);
        acc.z = fmaf(v1, b1.x, acc.z); acc.w = fmaf(v1, b1.y, acc.w);
        acc.x = fmaf(v2, a2.x, acc.x); acc.y = fmaf(v2, a2.y, acc.y);
        acc.z = fmaf(v2, b2.x, acc.z); acc.w = fmaf(v2, b2.y, acc.w);
        acc.x = fmaf(v3, a3.x, acc.x); acc.y = fmaf(v3, a3.y, acc.y);
        acc.z = fmaf(v3, b3.x, acc.z); acc.w = fmaf(v3, b3.y, acc.w);
    }
    for (; e < end; ++e) {
        int2 d0 = __ldg(&g_edges[e]);
        float v0 = __int_as_float(d0.y);
        uint2 r0 = __ldg((const uint2*)(h0 + ((size_t)d0.x << 7) + c));
        float2 a0 = __half22float2(*reinterpret_cast<__half2*>(&r0.x));
        float2 b0 = __half22float2(*reinterpret_cast<__half2*>(&r0.y));
        acc.x = fmaf(v0, a0.x, acc.x); acc.y = fmaf(v0, a0.y, acc.y);
        acc.z = fmaf(v0, b0.x, acc.z); acc.w = fmaf(v0, b0.y, acc.w);
    }
    __half2 o0 = __floats2half2_rn(fmaxf(acc.x, 0.f), fmaxf(acc.y, 0.f));
    __half2 o1 = __floats2half2_rn(fmaxf(acc.z, 0.f), fmaxf(acc.w, 0.f));
    uint2 ov = make_uint2(*reinterpret_cast<uint32_t*>(&o0), *reinterpret_cast<uint32_t*>(&o1));
    *reinterpret_cast<uint2*>(h1 + ((size_t)row << 7) + c) = ov;
}

// ---------------- spmm2: out = A @ h2_fp16 (fp32 out); half-warp per row ----------------
__global__ void spmm2_kernel(const __half* __restrict__ h2, float* __restrict__ out) {
    int gt = blockIdx.x * blockDim.x + threadIdx.x;
    int row = gt >> 4;
    if (row >= N_NODES) return;
    int lane16 = threadIdx.x & 15;
    int beg = g_row_ptr[row];
    int end = g_row_ptr[row + 1];
    int c = lane16 * 4;
    float4 acc = make_float4(0.f, 0.f, 0.f, 0.f);

    int e = beg;
    int e4 = beg + ((end - beg) & ~3);
    for (; e < e4; e += 4) {
        int2 d0 = __ldg(&g_edges[e + 0]);
        int2 d1 = __ldg(&g_edges[e + 1]);
        int2 d2 = __ldg(&g_edges[e + 2]);
        int2 d3 = __ldg(&g_edges[e + 3]);
        uint2 r0 = __ldg((const uint2*)(h2 + ((size_t)d0.x << 6) + c));
        uint2 r1 = __ldg((const uint2*)(h2 + ((size_t)d1.x << 6) + c));
        uint2 r2 = __ldg((const uint2*)(h2 + ((size_t)d2.x << 6) + c));
        uint2 r3 = __ldg((const uint2*)(h2 + ((size_t)d3.x << 6) + c));
        float v0 = __int_as_float(d0.y), v1 = __int_as_float(d1.y);
        float v2 = __int_as_float(d2.y), v3 = __int_as_float(d3.y);
        float2 a0 = __half22float2(*reinterpret_cast<__half2*>(&r0.x));
        float2 b0 = __half22float2(*reinterpret_cast<__half2*>(&r0.y));
        float2 a1 = __half22float2(*reinterpret_cast<__half2*>(&r1.x));
        float2 b1 = __half22float2(*reinterpret_cast<__half2*>(&r1.y));
        float2 a2 = __half22float2(*reinterpret_cast<__half2*>(&r2.x));
        float2 b2 = __half22float2(*reinterpret_cast<__half2*>(&r2.y));
        float2 a3 = __half22float2(*reinterpret_cast<__half2*>(&r3.x));
        float2 b3 = __half22float2(*reinterpret_cast<__half2*>(&r3.y));
        acc.x = fmaf(v0, a0.x, acc.x); acc.y = fmaf(v0, a0.y, acc.y);
        acc.z = fmaf(v0, b0.x, acc.z); acc.w = fmaf(v0, b0.y, acc.w);
        acc.x = fmaf(v1, a1.x, acc.x); acc.y = fmaf(v1, a1.y, acc.y);
        acc.z = fmaf(v1, b1.x, acc.z); acc.w = fmaf(v1, b1.y, acc.w);
        acc.x = fmaf(v2, a2.x, acc.x); acc.y = fmaf(v2, a2.y, acc.y);
        acc.z = fmaf(v2, b2.x, acc.z); acc.w = fmaf(v2, b2.y, acc.w);
        acc.x = fmaf(v3, a3.x, acc.x); acc.y = fmaf(v3, a3.y, acc.y);
        acc.z = fmaf(v3, b3.x, acc.z); acc.w = fmaf(v3, b3.y, acc.w);
    }
    for (; e < end; ++e) {
        int2 d0 = __ldg(&g_edges[e]);
        float v0 = __int_as_float(d0.y);
        uint2 r0 = __ldg((const uint2*)(h2 + ((size_t)d0.x << 6) + c));
        float2 a0 = __half22float2(*reinterpret_cast<__half2*>(&r0.x));
        float2 b0 = __half22float2(*reinterpret_cast<__half2*>(&r0.y));
        acc.x = fmaf(v0, a0.x, acc.x); acc.y = fmaf(v0, a0.y, acc.y);
        acc.z = fmaf(v0, b0.x, acc.z); acc.w = fmaf(v0, b0.y, acc.w);
    }
    *reinterpret_cast<float4*>(out + ((size_t)row << 6) + c) = acc;
}

// ---------------- launch ----------------
extern "C" void kernel_launch(void* const* d_in, const int* in_sizes, int n_in,
                              void* d_out, int out_size) {
    const float* x        = (const float*)d_in[0];
    const float* adj_vals = (const float*)d_in[1];
    const float* w1       = (const float*)d_in[2];
    const float* w2       = (const float*)d_in[3];
    const int*   edge_src = (const int*)d_in[4];
    const int*   edge_dst = (const int*)d_in[5];
    float* out = (float*)d_out;

    __half *p_h0, *p_h1, *p_h2;
    cudaGetSymbolAddress((void**)&p_h0, g_h0);
    cudaGetSymbolAddress((void**)&p_h1, g_h1);
    cudaGetSymbolAddress((void**)&p_h2, g_h2);

    const int TPB = 256;

    // CSR build
    zero_cnt_kernel<<<(N_NODES + TPB - 1) / TPB, TPB>>>();
    hist_kernel<<<(N_EDGES + TPB - 1) / TPB, TPB>>>(edge_dst);
    scan_reduce_kernel<<<SCAN_BLOCKS, 1024>>>();
    scan_partials_kernel<<<1, 128>>>();
    scan_final_kernel<<<SCAN_BLOCKS, 1024>>>();
    scatter_kernel<<<(N_EDGES + TPB - 1) / TPB, TPB>>>(edge_src, edge_dst, adj_vals);

    // layer 1: h0 = half(X @ W1)
    gemm_f32_h16out_kernel<32, HIDDEN><<<(N_NODES + 127) / 128, 256>>>(x, w1, p_h0, N_NODES, IN_DIM);
    // h1 = half(relu(A @ h0))
    spmm1_relu_kernel<<<(N_NODES * 32 + TPB - 1) / TPB, TPB>>>(p_h0, p_h1);
    // layer 2: h2 = half(h1 @ W2)
    gemm_h16_h16out_kernel<32, OUT_DIM><<<(N_NODES + 127) / 128, 256>>>(p_h1, w2, p_h2, N_NODES, HIDDEN);
    // out = A @ h2
    spmm2_kernel<<<(N_NODES * 16 + TPB - 1) / TPB, TPB>>>(p_h2, out);
}

// round 5
// speedup vs baseline: 1.9422x; 1.6390x over previous
#include <cuda_runtime.h>
#include <cuda_fp16.h>
#include <cstdint>

#define N_NODES 100000
#define N_EDGES 3200000
#define IN_DIM  256
#define HIDDEN  128
#define OUT_DIM 64

typedef unsigned long long ull;

// ---------------- device scratch (static; no cudaMalloc) ----------------
__device__ __align__(128) __half g_h0[(size_t)N_NODES * HIDDEN];  // X @ W1 (fp16)
__device__ __align__(128) __half g_h1[(size_t)N_NODES * HIDDEN];  // relu(A @ h0) (fp16)
__device__ __align__(128) __half g_h2[(size_t)N_NODES * OUT_DIM]; // h1 @ W2 (fp16)
__device__ __align__(128) __half g_w1h[IN_DIM * HIDDEN];
__device__ __align__(128) __half g_w2h[HIDDEN * OUT_DIM];
__device__ int  g_cnt[N_NODES];
__device__ int  g_row_ptr[N_NODES + 1];
__device__ int  g_cursor[N_NODES];
__device__ __align__(128) int2 g_edges[N_EDGES];                  // {src, val bits}
#define SCAN_BLOCKS 98
__device__ int  g_bsum[SCAN_BLOCKS];
__device__ int  g_boff[SCAN_BLOCKS];

// ---------------- helpers ----------------
__device__ __forceinline__ uint32_t smem_u32(const void* p) {
    return (uint32_t)__cvta_generic_to_shared(p);
}
__device__ __forceinline__ void ldmatrix_x4(uint32_t& r0, uint32_t& r1, uint32_t& r2,
                                            uint32_t& r3, uint32_t addr) {
    asm volatile("ldmatrix.sync.aligned.m8n8.x4.shared.b16 {%0,%1,%2,%3}, [%4];"
                 : "=r"(r0), "=r"(r1), "=r"(r2), "=r"(r3) : "r"(addr));
}
__device__ __forceinline__ void ldmatrix_x4_t(uint32_t& r0, uint32_t& r1, uint32_t& r2,
                                              uint32_t& r3, uint32_t addr) {
    asm volatile("ldmatrix.sync.aligned.m8n8.x4.trans.shared.b16 {%0,%1,%2,%3}, [%4];"
                 : "=r"(r0), "=r"(r1), "=r"(r2), "=r"(r3) : "r"(addr));
}
__device__ __forceinline__ void mma16816(float* d, const uint32_t* a, const uint32_t* b) {
    asm volatile("mma.sync.aligned.m16n8k16.row.col.f32.f16.f16.f32 "
                 "{%0,%1,%2,%3}, {%4,%5,%6,%7}, {%8,%9}, {%0,%1,%2,%3};"
                 : "+f"(d[0]), "+f"(d[1]), "+f"(d[2]), "+f"(d[3])
                 : "r"(a[0]), "r"(a[1]), "r"(a[2]), "r"(a[3]), "r"(b[0]), "r"(b[1]));
}
__device__ __forceinline__ uint32_t h2bits(__half2 h) {
    return *reinterpret_cast<uint32_t*>(&h);
}

// ---------------- CSR build ----------------
__global__ void zero_cnt_kernel() {
    int i = blockIdx.x * blockDim.x + threadIdx.x;
    if (i < N_NODES) g_cnt[i] = 0;
}

__global__ void hist_kernel(const int* __restrict__ edge_dst) {
    int e = blockIdx.x * blockDim.x + threadIdx.x;
    if (e < N_EDGES) atomicAdd(&g_cnt[edge_dst[e]], 1);
}

__device__ __forceinline__ int warp_incl_scan(int v) {
    int lane = threadIdx.x & 31;
    #pragma unroll
    for (int o = 1; o < 32; o <<= 1) {
        int n = __shfl_up_sync(0xffffffffu, v, o);
        if (lane >= o) v += n;
    }
    return v;
}

__global__ void scan_reduce_kernel() {
    int i = blockIdx.x * 1024 + threadIdx.x;
    int v = (i < N_NODES) ? g_cnt[i] : 0;
    #pragma unroll
    for (int o = 16; o > 0; o >>= 1) v += __shfl_down_sync(0xffffffffu, v, o);
    __shared__ int ws[32];
    int wid = threadIdx.x >> 5, lane = threadIdx.x & 31;
    if (lane == 0) ws[wid] = v;
    __syncthreads();
    if (wid == 0) {
        v = ws[lane];
        #pragma unroll
        for (int o = 16; o > 0; o >>= 1) v += __shfl_down_sync(0xffffffffu, v, o);
        if (lane == 0) g_bsum[blockIdx.x] = v;
    }
}

__global__ void scan_partials_kernel() {
    int t = threadIdx.x;
    int v = (t < SCAN_BLOCKS) ? g_bsum[t] : 0;
    int incl = warp_incl_scan(v);
    __shared__ int ws[4];
    int wid = t >> 5, lane = t & 31;
    if (lane == 31) ws[wid] = incl;
    __syncthreads();
    int off = 0;
    #pragma unroll
    for (int w = 0; w < 4; ++w) if (w < wid) off += ws[w];
    incl += off;
    if (t < SCAN_BLOCKS) g_boff[t] = incl - v;  // exclusive
    if (t == 0) g_row_ptr[N_NODES] = N_EDGES;
}

__global__ void scan_final_kernel() {
    int i = blockIdx.x * 1024 + threadIdx.x;
    int v = (i < N_NODES) ? g_cnt[i] : 0;
    int incl = warp_incl_scan(v);
    __shared__ int ws[32];
    int wid = threadIdx.x >> 5, lane = threadIdx.x & 31;
    if (lane == 31) ws[wid] = incl;
    __syncthreads();
    if (wid == 0) { int w = warp_incl_scan(ws[lane]); ws[lane] = w; }
    __syncthreads();
    int off = g_boff[blockIdx.x] + ((wid > 0) ? ws[wid - 1] : 0);
    if (i < N_NODES) {
        int ex = off + incl - v;
        g_row_ptr[i] = ex;
        g_cursor[i]  = ex;
    }
}

__global__ void scatter_kernel(const int* __restrict__ edge_src,
                               const int* __restrict__ edge_dst,
                               const float* __restrict__ adj_vals) {
    int e = blockIdx.x * blockDim.x + threadIdx.x;
    if (e >= N_EDGES) return;
    int d = edge_dst[e];
    int pos = atomicAdd(&g_cursor[d], 1);
    g_edges[pos] = make_int2(edge_src[e], __float_as_int(adj_vals[e]));
}

// ---------------- weight convert ----------------
__global__ void convert_w_kernel(const float* __restrict__ w1, const float* __restrict__ w2) {
    int i = blockIdx.x * blockDim.x + threadIdx.x;
    if (i < IN_DIM * HIDDEN) g_w1h[i] = __float2half_rn(w1[i]);
    if (i < HIDDEN * OUT_DIM) g_w2h[i] = __float2half_rn(w2[i]);
}

// ---------------- tensor-core GEMM: C[M,TN] = half(A[M,K] @ B[K,TN]) ----------------
// 256 threads; block tile 128 x TN; full K resident in dynamic smem.
// warps: 4 (m) x 2 (n); warp tile 32 x TN/2; HMMA m16n8k16, fp32 accum.
template<int K_DIM, int TN, bool A_IS_F32>
__global__ __launch_bounds__(256)
void gemm_tc_kernel(const void* __restrict__ Ain, const __half* __restrict__ Bh,
                    __half* __restrict__ C, int M) {
    extern __shared__ __half sm[];
    constexpr int AP = K_DIM + 8;
    constexpr int BP = TN + 8;
    __half* As = sm;                       // [128][AP]
    __half* Bs = sm + 128 * AP;            // [K_DIM][BP]

    const int t = threadIdx.x;
    const int row0 = blockIdx.x * 128;

    // load B (whole weight matrix), 8 halves per thread-iter
    #pragma unroll
    for (int i = t; i < K_DIM * TN / 8; i += 256) {
        int k  = i / (TN / 8);
        int n8 = i % (TN / 8);
        uint4 v = __ldg((const uint4*)(Bh + (size_t)k * TN + n8 * 8));
        *reinterpret_cast<uint4*>(Bs + k * BP + n8 * 8) = v;
    }
    // load A tile (convert fp32 -> fp16 if needed)
    if (A_IS_F32) {
        const float* A = (const float*)Ain;
        #pragma unroll
        for (int i = t; i < 128 * K_DIM / 4; i += 256) {
            int m  = i / (K_DIM / 4);
            int k4 = i % (K_DIM / 4);
            int gr = row0 + m;
            float4 v = make_float4(0.f, 0.f, 0.f, 0.f);
            if (gr < M) v = __ldg((const float4*)(A + (size_t)gr * K_DIM + k4 * 4));
            uint2 o = make_uint2(h2bits(__floats2half2_rn(v.x, v.y)),
                                 h2bits(__floats2half2_rn(v.z, v.w)));
            *reinterpret_cast<uint2*>(As + m * AP + k4 * 4) = o;
        }
    } else {
        const __half* A = (const __half*)Ain;
        #pragma unroll
        for (int i = t; i < 128 * K_DIM / 8; i += 256) {
            int m  = i / (K_DIM / 8);
            int k8 = i % (K_DIM / 8);
            int gr = row0 + m;
            uint4 v = make_uint4(0u, 0u, 0u, 0u);
            if (gr < M) v = __ldg((const uint4*)(A + (size_t)gr * K_DIM + k8 * 8));
            *reinterpret_cast<uint4*>(As + m * AP + k8 * 8) = v;
        }
    }
    __syncthreads();

    const int wid  = t >> 5;
    const int lane = t & 31;
    const int wm = wid & 3;                // 4 m-warps
    const int wn = wid >> 2;               // 2 n-warps
    const int m_base = wm * 32;
    const int n_base = wn * (TN / 2);
    constexpr int NTILES = TN / 2 / 8;     // 8 (TN=128) or 4 (TN=64)

    float acc[2][NTILES][4];
    #pragma unroll
    for (int i = 0; i < 2; ++i)
        #pragma unroll
        for (int j = 0; j < NTILES; ++j)
            #pragma unroll
            for (int q = 0; q < 4; ++q) acc[i][j][q] = 0.f;

    // precompute lane-dependent ldmatrix offsets
    const int a_row_off = lane & 15;             // row within 16-row tile
    const int a_col_off = (lane >> 4) * 8;       // k half-select
    const int b_krow = (lane & 7) + ((lane >> 3) & 1) * 8;
    const int b_ncol = (lane >> 4) * 8;

    #pragma unroll
    for (int ks = 0; ks < K_DIM / 16; ++ks) {
        const int k0 = ks * 16;
        uint32_t afrag[2][4];
        #pragma unroll
        for (int i = 0; i < 2; ++i) {
            int r = m_base + i * 16 + a_row_off;
            uint32_t addr = smem_u32(As + r * AP + k0 + a_col_off);
            ldmatrix_x4(afrag[i][0], afrag[i][1], afrag[i][2], afrag[i][3], addr);
        }
        uint32_t bfrag[NTILES][2];
        #pragma unroll
        for (int j = 0; j < NTILES / 2; ++j) {
            int kr = k0 + b_krow;
            int nc = n_base + j * 16 + b_ncol;
            uint32_t addr = smem_u32(Bs + kr * BP + nc);
            ldmatrix_x4_t(bfrag[2 * j][0], bfrag[2 * j][1],
                          bfrag[2 * j + 1][0], bfrag[2 * j + 1][1], addr);
        }
        #pragma unroll
        for (int i = 0; i < 2; ++i)
            #pragma unroll
            for (int j = 0; j < NTILES; ++j)
                mma16816(acc[i][j], afrag[i], bfrag[j]);
    }

    // epilogue: fp32 -> fp16, 4B stores
    const int erow = lane >> 2;
    const int ecol = (lane & 3) * 2;
    #pragma unroll
    for (int i = 0; i < 2; ++i) {
        int r0 = row0 + m_base + i * 16 + erow;
        #pragma unroll
        for (int j = 0; j < NTILES; ++j) {
            int col = n_base + j * 8 + ecol;
            if (r0 < M) {
                __half2 h = __floats2half2_rn(acc[i][j][0], acc[i][j][1]);
                *reinterpret_cast<uint32_t*>(C + (size_t)r0 * TN + col) = h2bits(h);
            }
            if (r0 + 8 < M) {
                __half2 h = __floats2half2_rn(acc[i][j][2], acc[i][j][3]);
                *reinterpret_cast<uint32_t*>(C + (size_t)(r0 + 8) * TN + col) = h2bits(h);
            }
        }
    }
}

// ---------------- spmm1: h1 = relu(A @ h0_fp16), fp16 out; warp-per-row ----------------
__global__ void spmm1_relu_kernel(const __half* __restrict__ h0, __half* __restrict__ h1) {
    int row = (int)((blockIdx.x * blockDim.x + threadIdx.x) >> 5);
    if (row >= N_NODES) return;
    int lane = threadIdx.x & 31;
    int beg = g_row_ptr[row];
    int end = g_row_ptr[row + 1];
    int c = lane * 4;
    float4 acc = make_float4(0.f, 0.f, 0.f, 0.f);

    int e = beg;
    int e4 = beg + ((end - beg) & ~3);
    for (; e < e4; e += 4) {
        int2 d0 = __ldg(&g_edges[e + 0]);
        int2 d1 = __ldg(&g_edges[e + 1]);
        int2 d2 = __ldg(&g_edges[e + 2]);
        int2 d3 = __ldg(&g_edges[e + 3]);
        uint2 r0 = __ldg((const uint2*)(h0 + ((size_t)d0.x << 7) + c));
        uint2 r1 = __ldg((const uint2*)(h0 + ((size_t)d1.x << 7) + c));
        uint2 r2 = __ldg((const uint2*)(h0 + ((size_t)d2.x << 7) + c));
        uint2 r3 = __ldg((const uint2*)(h0 + ((size_t)d3.x << 7) + c));
        float v0 = __int_as_float(d0.y), v1 = __int_as_float(d1.y);
        float v2 = __int_as_float(d2.y), v3 = __int_as_float(d3.y);
        float2 a0 = __half22float2(*reinterpret_cast<__half2*>(&r0.x));
        float2 b0 = __half22float2(*reinterpret_cast<__half2*>(&r0.y));
        float2 a1 = __half22float2(*reinterpret_cast<__half2*>(&r1.x));
        float2 b1 = __half22float2(*reinterpret_cast<__half2*>(&r1.y));
        float2 a2 = __half22float2(*reinterpret_cast<__half2*>(&r2.x));
        float2 b2 = __half22float2(*reinterpret_cast<__half2*>(&r2.y));
        float2 a3 = __half22float2(*reinterpret_cast<__half2*>(&r3.x));
        float2 b3 = __half22float2(*reinterpret_cast<__half2*>(&r3.y));
        acc.x = fmaf(v0, a0.x, acc.x); acc.y = fmaf(v0, a0.y, acc.y);
        acc.z = fmaf(v0, b0.x, acc.z); acc.w = fmaf(v0, b0.y, acc.w);
        acc.x = fmaf(v1, a1.x, acc.x); acc.y = fmaf(v1, a1.y, acc.y);
        acc.z = fmaf(v1, b1.x, acc.z); acc.w = fmaf(v1, b1.y, acc.w);
        acc.x = fmaf(v2, a2.x, acc.x); acc.y = fmaf(v2, a2.y, acc.y);
        acc.z = fmaf(v2, b2.x, acc.z); acc.w = fmaf(v2, b2.y, acc.w);
        acc.x = fmaf(v3, a3.x, acc.x); acc.y = fmaf(v3, a3.y, acc.y);
        acc.z = fmaf(v3, b3.x, acc.z); acc.w = fmaf(v3, b3.y, acc.w);
    }
    for (; e < end; ++e) {
        int2 d0 = __ldg(&g_edges[e]);
        float v0 = __int_as_float(d0.y);
        uint2 r0 = __ldg((const uint2*)(h0 + ((size_t)d0.x << 7) + c));
        float2 a0 = __half22float2(*reinterpret_cast<__half2*>(&r0.x));
        float2 b0 = __half22float2(*reinterpret_cast<__half2*>(&r0.y));
        acc.x = fmaf(v0, a0.x, acc.x); acc.y = fmaf(v0, a0.y, acc.y);
        acc.z = fmaf(v0, b0.x, acc.z); acc.w = fmaf(v0, b0.y, acc.w);
    }
    __half2 o0 = __floats2half2_rn(fmaxf(acc.x, 0.f), fmaxf(acc.y, 0.f));
    __half2 o1 = __floats2half2_rn(fmaxf(acc.z, 0.f), fmaxf(acc.w, 0.f));
    uint2 ov = make_uint2(h2bits(o0), h2bits(o1));
    *reinterpret_cast<uint2*>(h1 + ((size_t)row << 7) + c) = ov;
}

// ---------------- spmm2: out = A @ h2_fp16 (fp32 out); half-warp per row ----------------
__global__ void spmm2_kernel(const __half* __restrict__ h2, float* __restrict__ out) {
    int gt = blockIdx.x * blockDim.x + threadIdx.x;
    int row = gt >> 4;
    if (row >= N_NODES) return;
    int lane16 = threadIdx.x & 15;
    int beg = g_row_ptr[row];
    int end = g_row_ptr[row + 1];
    int c = lane16 * 4;
    float4 acc = make_float4(0.f, 0.f, 0.f, 0.f);

    int e = beg;
    int e4 = beg + ((end - beg) & ~3);
    for (; e < e4; e += 4) {
        int2 d0 = __ldg(&g_edges[e + 0]);
        int2 d1 = __ldg(&g_edges[e + 1]);
        int2 d2 = __ldg(&g_edges[e + 2]);
        int2 d3 = __ldg(&g_edges[e + 3]);
        uint2 r0 = __ldg((const uint2*)(h2 + ((size_t)d0.x << 6) + c));
        uint2 r1 = __ldg((const uint2*)(h2 + ((size_t)d1.x << 6) + c));
        uint2 r2 = __ldg((const uint2*)(h2 + ((size_t)d2.x << 6) + c));
        uint2 r3 = __ldg((const uint2*)(h2 + ((size_t)d3.x << 6) + c));
        float v0 = __int_as_float(d0.y), v1 = __int_as_float(d1.y);
        float v2 = __int_as_float(d2.y), v3 = __int_as_float(d3.y);
        float2 a0 = __half22float2(*reinterpret_cast<__half2*>(&r0.x));
        float2 b0 = __half22float2(*reinterpret_cast<__half2*>(&r0.y));
        float2 a1 = __half22float2(*reinterpret_cast<__half2*>(&r1.x));
        float2 b1 = __half22float2(*reinterpret_cast<__half2*>(&r1.y));
        float2 a2 = __half22float2(*reinterpret_cast<__half2*>(&r2.x));
        float2 b2 = __half22float2(*reinterpret_cast<__half2*>(&r2.y));
        float2 a3 = __half22float2(*reinterpret_cast<__half2*>(&r3.x));
        float2 b3 = __half22float2(*reinterpret_cast<__half2*>(&r3.y));
        acc.x = fmaf(v0, a0.x, acc.x); acc.y = fmaf(v0, a0.y, acc.y);
        acc.z = fmaf(v0, b0.x, acc.z); acc.w = fmaf(v0, b0.y, acc.w);
        acc.x = fmaf(v1, a1.x, acc.x); acc.y = fmaf(v1, a1.y, acc.y);
        acc.z = fmaf(v1, b1.x, acc.z); acc.w = fmaf(v1, b1.y, acc.w);
        acc.x = fmaf(v2, a2.x, acc.x); acc.y = fmaf(v2, a2.y, acc.y);
        acc.z = fmaf(v2, b2.x, acc.z); acc.w = fmaf(v2, b2.y, acc.w);
        acc.x = fmaf(v3, a3.x, acc.x); acc.y = fmaf(v3, a3.y, acc.y);
        acc.z = fmaf(v3, b3.x, acc.z); acc.w = fmaf(v3, b3.y, acc.w);
    }
    for (; e < end; ++e) {
        int2 d0 = __ldg(&g_edges[e]);
        float v0 = __int_as_float(d0.y);
        uint2 r0 = __ldg((const uint2*)(h2 + ((size_t)d0.x << 6) + c));
        float2 a0 = __half22float2(*reinterpret_cast<__half2*>(&r0.x));
        float2 b0 = __half22float2(*reinterpret_cast<__half2*>(&r0.y));
        acc.x = fmaf(v0, a0.x, acc.x); acc.y = fmaf(v0, a0.y, acc.y);
        acc.z = fmaf(v0, b0.x, acc.z); acc.w = fmaf(v0, b0.y, acc.w);
    }
    *reinterpret_cast<float4*>(out + ((size_t)row << 6) + c) = acc;
}

// ---------------- launch ----------------
extern "C" void kernel_launch(void* const* d_in, const int* in_sizes, int n_in,
                              void* d_out, int out_size) {
    const float* x        = (const float*)d_in[0];
    const float* adj_vals = (const float*)d_in[1];
    const float* w1       = (const float*)d_in[2];
    const float* w2       = (const float*)d_in[3];
    const int*   edge_src = (const int*)d_in[4];
    const int*   edge_dst = (const int*)d_in[5];
    float* out = (float*)d_out;

    __half *p_h0, *p_h1, *p_h2, *p_w1h, *p_w2h;
    cudaGetSymbolAddress((void**)&p_h0, g_h0);
    cudaGetSymbolAddress((void**)&p_h1, g_h1);
    cudaGetSymbolAddress((void**)&p_h2, g_h2);
    cudaGetSymbolAddress((void**)&p_w1h, g_w1h);
    cudaGetSymbolAddress((void**)&p_w2h, g_w2h);

    const int TPB = 256;

    // dynamic smem sizes
    const int SMEM1 = (128 * (IN_DIM + 8) + IN_DIM * (HIDDEN + 8)) * (int)sizeof(__half);
    const int SMEM2 = (128 * (HIDDEN + 8) + HIDDEN * (OUT_DIM + 8)) * (int)sizeof(__half);
    cudaFuncSetAttribute(gemm_tc_kernel<IN_DIM, HIDDEN, true>,
                         cudaFuncAttributeMaxDynamicSharedMemorySize, SMEM1);
    cudaFuncSetAttribute(gemm_tc_kernel<HIDDEN, OUT_DIM, false>,
                         cudaFuncAttributeMaxDynamicSharedMemorySize, SMEM2);

    // CSR build
    zero_cnt_kernel<<<(N_NODES + TPB - 1) / TPB, TPB>>>();
    hist_kernel<<<(N_EDGES + TPB - 1) / TPB, TPB>>>(edge_dst);
    scan_reduce_kernel<<<SCAN_BLOCKS, 1024>>>();
    scan_partials_kernel<<<1, 128>>>();
    scan_final_kernel<<<SCAN_BLOCKS, 1024>>>();
    scatter_kernel<<<(N_EDGES + TPB - 1) / TPB, TPB>>>(edge_src, edge_dst, adj_vals);

    // weights -> fp16
    convert_w_kernel<<<(IN_DIM * HIDDEN + TPB - 1) / TPB, TPB>>>(w1, w2);

    const int GBLK = (N_NODES + 127) / 128;
    // layer 1: h0 = half(X @ W1)   (tensor cores)
    gemm_tc_kernel<IN_DIM, HIDDEN, true><<<GBLK, 256, SMEM1>>>(x, p_w1h, p_h0, N_NODES);
    // h1 = half(relu(A @ h0))
    spmm1_relu_kernel<<<(N_NODES * 32 + TPB - 1) / TPB, TPB>>>(p_h0, p_h1);
    // layer 2: h2 = half(h1 @ W2)  (tensor cores)
    gemm_tc_kernel<HIDDEN, OUT_DIM, false><<<GBLK, 256, SMEM2>>>(p_h1, p_w2h, p_h2, N_NODES);
    // out = A @ h2
    spmm2_kernel<<<(N_NODES * 16 + TPB - 1) / TPB, TPB>>>(p_h2, out);
}